// round 10
// baseline (speedup 1.0000x reference)
#include <cuda_runtime.h>
#include <cuda_fp16.h>
#include <cstdint>

#define SM_STRIDE 136            // fp16 elems per smem row (conflict-free ldmatrix)

// smem byte offsets (per CTA ~55.5 KB -> 3 CTAs/SM)
#define WS_OFF    0                                  // W fp16: 128*136*2 = 34816
#define XS_OFF    34816                              // 2 quad buffers, 32 rows each
#define XS_QUAD   8704                               // 32*136*2
#define XN2_OFF   (XS_OFF + 2*XS_QUAD)               // float[2][32]
#define DS_OFF    (XN2_OFF + 256)                    // float[2][32]
#define US_OFF    (DS_OFF + 256)                     // float[128] u = W^T h
#define HV_OFF    (US_OFF + 512)                     // float[128]
#define RED1_OFF  (HV_OFF + 512)                     // float4[2][4][2][8] = 2048
#define RED2_OFF  (RED1_OFF + 2048)                  // float2[2][4][2][8] = 1024
#define SC_OFF    (RED2_OFF + 1024)                  // float[4]
#define SMEM_BYTES (SC_OFF + 16)

#define MINN  1e-15f
#define MAXN  0.996f
#define ATLIM (1.0f - 1e-7f)

#define LDSM4(R, addr)                                                        \
    asm volatile("ldmatrix.sync.aligned.m8n8.x4.shared.b16 {%0,%1,%2,%3}, [%4];" \
                 : "=r"((R)[0]), "=r"((R)[1]), "=r"((R)[2]), "=r"((R)[3])     \
                 : "r"(addr) : "memory")

#define QUAD_BAR() asm volatile("bar.sync %0, 128;" :: "r"(barid) : "memory")

__device__ __forceinline__ void mma16816(float* d, const uint32_t* a, const uint32_t* b) {
    asm volatile(
        "mma.sync.aligned.m16n8k16.row.col.f32.f16.f16.f32 "
        "{%0,%1,%2,%3}, {%4,%5,%6,%7}, {%8,%9}, {%0,%1,%2,%3};"
        : "+f"(d[0]), "+f"(d[1]), "+f"(d[2]), "+f"(d[3])
        : "r"(a[0]), "r"(a[1]), "r"(a[2]), "r"(a[3]), "r"(b[0]), "r"(b[1]));
}

__device__ __forceinline__ float artanh_c(float x) {
    float xc = fminf(x, ATLIM);
    return 0.5f * (log1pf(xc) - log1pf(-xc));
}

__device__ __forceinline__ void row_chain(float S2, float D, float xn2v, float y2,
                                          float& pa, float& pb, float& Lr) {
    float xn  = fmaxf(sqrtf(xn2v), MINN);
    float mxn = fmaxf(sqrtf(S2), MINN);
    float atx = artanh_c(xn);
    float r1  = tanhf(mxn / xn * atx);
    float scale1 = r1 / mxn;
    float resn = r1;
    float pn = fmaxf(resn, MINN);
    if (pn > MAXN) { scale1 *= MAXN / pn; resn = MAXN; }
    float x2 = resn * resn;
    float xy = scale1 * D;
    float num1 = 1.f + 2.f*xy + y2;
    float den  = fmaxf(1.f + 2.f*xy + x2*y2, MINN);
    float aC = num1 / den;
    float bC = (1.f - x2) / den;
    float o2n2 = aC*aC*x2 + 2.f*aC*bC*xy + bC*bC*y2;
    float o2n  = sqrtf(fmaxf(o2n2, 0.f));
    float g = 1.f;
    float pn2 = fmaxf(o2n, MINN);
    if (pn2 > MAXN) { g = MAXN / pn2; pn2 = MAXN; }
    Lr = artanh_c(pn2) / pn2;
    pa = g * aC * scale1;
    pb = g * bC;
}

__device__ __forceinline__ float final_scale(float ps, float Lr) {
    float P  = sqrtf(fmaxf(ps, 0.f));
    float un = fmaxf(Lr * P, MINN);
    float th = tanhf(un);
    float f  = th / un * Lr;
    if (th > MAXN) f *= MAXN / th;
    return f;
}

// fp32x4 -> fp16x4 (rn) into padded-stride smem
__device__ __forceinline__ void store_h16(__half* dst, int row, int col, float4 v) {
    __half2 h01 = __floats2half2_rn(v.x, v.y);
    __half2 h23 = __floats2half2_rn(v.z, v.w);
    uint2 ph;
    ph.x = *reinterpret_cast<uint32_t*>(&h01);
    ph.y = *reinterpret_cast<uint32_t*>(&h23);
    *(uint2*)(dst + row * SM_STRIDE + col) = ph;
}

__global__ void __launch_bounds__(256, 3)
blinear_fused(const float* __restrict__ X, const float* __restrict__ W,
              const float* __restrict__ B, float* __restrict__ OUT, int nUnits)
{
    extern __shared__ char smem[];
    __half* ws    = (__half*)(smem + WS_OFF);
    float* xn2_s  = (float*)(smem + XN2_OFF);
    float* D_s    = (float*)(smem + DS_OFF);
    float* us     = (float*)(smem + US_OFF);
    float* hvec   = (float*)(smem + HV_OFF);
    float4* red1  = (float4*)(smem + RED1_OFF);
    float2* red2  = (float2*)(smem + RED2_OFF);
    float* SC     = (float*)(smem + SC_OFF);

    const int tid  = threadIdx.x;
    const int lane = tid & 31;
    const int w    = tid >> 5;   // 0..7
    const int qd   = w >> 2;     // quad 0/1 : owns a 32-row unit
    const int wq   = w & 3;      // warp-in-quad : cols 32*wq .. 32*wq+31
    const int tq   = lane & 3;
    const int q    = lane >> 2;
    const int barid = 1 + qd;
    const int lr   = lane >> 3;  // 0..3
    const int lc   = lane & 7;   // 0..7
    const int rq   = wq * 8;     // this warp's 8 load-rows within the quad

    __half* xs   = (__half*)(smem + XS_OFF + qd * XS_QUAD);
    float* xn2q  = xn2_s + qd * 32;
    float* Dq    = D_s + qd * 32;

    // ---- once per CTA: W (128x128) -> fp16 in smem ----
    #pragma unroll
    for (int j = 0; j < 16; ++j) {
        int row = j * 8 + w;
        float4 wv = *(const float4*)(W + (size_t)row * 128 + lane * 4);
        store_h16(ws, row, lane * 4, wv);
    }

    // ---- once per CTA: hyp_bias h = proj(expmap0(b)) (warp 0) ----
    if (w == 0) {
        float4 bv = *(const float4*)(B + lane * 4);
        float sq = bv.x*bv.x + bv.y*bv.y + bv.z*bv.z + bv.w*bv.w;
        #pragma unroll
        for (int o = 16; o; o >>= 1) sq += __shfl_xor_sync(0xffffffffu, sq, o);
        float bn2 = sq;
        float bn  = fmaxf(sqrtf(bn2), MINN);
        float th  = tanhf(bn);
        float hs  = th / bn;
        float hn  = hs * sqrtf(bn2);
        float pn  = fmaxf(hn, MINN);
        if (pn > MAXN) hs *= MAXN / pn;
        if (lane == 0) SC[0] = hs * hs * bn2;
        *(float4*)(hvec + lane * 4) =
            make_float4(hs*bv.x, hs*bv.y, hs*bv.z, hs*bv.w);
    }
    __syncthreads();

    const float y2 = SC[0];
    const bool hasB = (y2 != 0.0f);   // uniform across grid

    // ---- once per CTA (only if bias nonzero): u = W^T h ----
    if (hasB && tid < 128) {
        float a = 0.f;
        for (int j = 0; j < 128; ++j)
            a = fmaf(hvec[j], W[(size_t)j * 128 + tid], a);
        us[tid] = a;
    }
    __syncthreads();

    uint32_t s_xs = (uint32_t)__cvta_generic_to_shared(xs);
    uint32_t s_ws = (uint32_t)__cvta_generic_to_shared(ws);

    // A fragments: quad rows 0..31 (two m16 frags, shared by 4 warps)
    const uint32_t aoff0 = (uint32_t)((((lane & 15)) * SM_STRIDE + (lane >> 4) * 8) * 2);
    const uint32_t aoff1 = aoff0 + 16 * SM_STRIDE * 2;
    // B fragments: 2 n16 groups covering this warp's 32 cols
    const int bg  = lane >> 3;
    const int b_n = ((bg >> 1) << 3) + (lane & 7);
    const int b_k = (bg & 1) * 8;
    uint32_t boff[2];
    #pragma unroll
    for (int g = 0; g < 2; ++g)
        boff[g] = (uint32_t)(((32*wq + 16*g + b_n) * SM_STRIDE + b_k) * 2);

    // exchange slots: ((qd*4 + ww)*2 + mt)*8 + q
    const int slot_me = (qd*4 + wq)*16;
    const int slot_qb = qd*4*16;           // base of this quad's 4 warps

    const int unitStride = gridDim.x * 2;
    const int colbase = ((lc * 4) + (lr * 8)) & 31;

    // ================= persistent unit loop (32-row units per quad) =========
    for (int unit = blockIdx.x * 2 + qd; unit < nUnits; unit += unitStride) {
        const size_t unitRow = (size_t)unit * 32;

        // ---- load this warp's 8 rows (full 128 cols), norms, fp16 cvt ----
        #pragma unroll
        for (int j = 0; j < 2; ++j) {
            const int row = rq + 4*j + lr;
            float sq = 0.f, dh = 0.f;
            #pragma unroll
            for (int i = 0; i < 4; ++i) {
                const int col = colbase + 32*i;
                float4 v = *(const float4*)(X + (unitRow + row) * 128 + col);
                sq = fmaf(v.x, v.x, fmaf(v.y, v.y, fmaf(v.z, v.z, fmaf(v.w, v.w, sq))));
                if (hasB) {
                    float4 u4 = *(const float4*)(us + col);
                    dh = fmaf(v.x, u4.x, fmaf(v.y, u4.y, fmaf(v.z, u4.z, fmaf(v.w, u4.w, dh))));
                }
                store_h16(xs, row, col, v);
            }
            #pragma unroll
            for (int o = 1; o <= 4; o <<= 1) {
                sq += __shfl_xor_sync(0xffffffffu, sq, o);
                if (hasB) dh += __shfl_xor_sync(0xffffffffu, dh, o);
            }
            if (lc == 0) { xn2q[row] = sq; Dq[row] = dh; }
        }

        // L2 prefetch next unit's 8 rows for this warp (4 KB)
        {
            int nu = unit + unitStride;
            if (nu < nUnits) {
                const float* pf = X + ((size_t)nu * 32 + rq) * 128 + (size_t)lane * 32;
                asm volatile("prefetch.global.L2 [%0];" :: "l"(pf));
            }
        }

        QUAD_BAR();   // A: xs + xn2 + D visible within quad

        // ---- MMA: 32 rows x 32 cols, single fp16 term ----
        float acc[2][4][4];
        #pragma unroll
        for (int mt = 0; mt < 2; ++mt)
            #pragma unroll
            for (int nt = 0; nt < 4; ++nt)
                #pragma unroll
                for (int r = 0; r < 4; ++r) acc[mt][nt][r] = 0.f;

        #pragma unroll
        for (int k = 0; k < 8; ++k) {
            const uint32_t kb = k * 32;
            uint32_t ah0[4], ah1[4], bh[2][4];
            LDSM4(ah0, s_xs + aoff0 + kb);
            LDSM4(ah1, s_xs + aoff1 + kb);
            LDSM4(bh[0], s_ws + boff[0] + kb);
            LDSM4(bh[1], s_ws + boff[1] + kb);
            #pragma unroll
            for (int nt = 0; nt < 4; ++nt) {
                const int g = nt >> 1, o = (nt & 1) * 2;
                mma16816(acc[0][nt], ah0, &bh[g][o]);
                mma16816(acc[1][nt], ah1, &bh[g][o]);
            }
        }

        // ---- phase 1: per-row sum(mx^2) AND sum(relu(mx)^2) ----
        #pragma unroll
        for (int mt = 0; mt < 2; ++mt) {
            float sq0 = 0.f, r0 = 0.f, sq1 = 0.f, r1 = 0.f;
            #pragma unroll
            for (int nt = 0; nt < 4; ++nt) {
                float v0 = acc[mt][nt][0], v1 = acc[mt][nt][1];
                float v2 = acc[mt][nt][2], v3 = acc[mt][nt][3];
                sq0 = fmaf(v0, v0, fmaf(v1, v1, sq0));
                sq1 = fmaf(v2, v2, fmaf(v3, v3, sq1));
                float p0 = fmaxf(v0, 0.f), p1 = fmaxf(v1, 0.f);
                float p2 = fmaxf(v2, 0.f), p3 = fmaxf(v3, 0.f);
                r0 = fmaf(p0, p0, fmaf(p1, p1, r0));
                r1 = fmaf(p2, p2, fmaf(p3, p3, r1));
            }
            #pragma unroll
            for (int o = 1; o <= 2; o <<= 1) {
                sq0 += __shfl_xor_sync(0xffffffffu, sq0, o);
                r0  += __shfl_xor_sync(0xffffffffu, r0,  o);
                sq1 += __shfl_xor_sync(0xffffffffu, sq1, o);
                r1  += __shfl_xor_sync(0xffffffffu, r1,  o);
            }
            if (tq == 0) red1[slot_me + mt*8 + q] = make_float4(sq0, r0, sq1, r1);
        }
        QUAD_BAR();   // B

        if (!hasB) {
            // ---- fast path: relu(pa*mx) = pa*relu(mx), no second exchange ----
            #pragma unroll
            for (int mt = 0; mt < 2; ++mt) {
                float S2t[2] = {0.f, 0.f}, Rt[2] = {0.f, 0.f};
                #pragma unroll
                for (int ww = 0; ww < 4; ++ww) {
                    float4 e = red1[slot_qb + ww*16 + mt*8 + q];
                    S2t[0] += e.x; Rt[0] += e.y;
                    S2t[1] += e.z; Rt[1] += e.w;
                }
                #pragma unroll
                for (int rh = 0; rh < 2; ++rh) {
                    const int rloc = 16*mt + 8*rh + q;
                    float pa, pb, Lr;
                    row_chain(S2t[rh], 0.f, xn2q[rloc], y2, pa, pb, Lr);
                    float fac = final_scale(pa * pa * Rt[rh], Lr) * pa;
                    float* outp = OUT + (unitRow + rloc) * 128 + 32*wq + 2*tq;
                    #pragma unroll
                    for (int nt = 0; nt < 4; ++nt) {
                        float2 o;
                        o.x = fac * fmaxf(acc[mt][nt][2*rh],     0.f);
                        o.y = fac * fmaxf(acc[mt][nt][2*rh + 1], 0.f);
                        *(float2*)(outp + 8*nt) = o;
                    }
                }
            }
        } else {
            // ---- general path: p = relu(pa*mx + pb*h), second exchange ----
            float paL[2][2], LrL[2][2];
            #pragma unroll
            for (int mt = 0; mt < 2; ++mt) {
                float S2t[2] = {0.f, 0.f};
                #pragma unroll
                for (int ww = 0; ww < 4; ++ww) {
                    float4 e = red1[slot_qb + ww*16 + mt*8 + q];
                    S2t[0] += e.x; S2t[1] += e.z;
                }
                float psv[2];
                #pragma unroll
                for (int rh = 0; rh < 2; ++rh) {
                    const int rloc = 16*mt + 8*rh + q;
                    float pa, pb, Lr;
                    row_chain(S2t[rh], Dq[rloc], xn2q[rloc], y2, pa, pb, Lr);
                    paL[mt][rh] = pa; LrL[mt][rh] = Lr;
                    float ps = 0.f;
                    #pragma unroll
                    for (int nt = 0; nt < 4; ++nt) {
                        float h0 = hvec[32*wq + 8*nt + 2*tq];
                        float h1 = hvec[32*wq + 8*nt + 2*tq + 1];
                        float p0 = fmaxf(fmaf(pa, acc[mt][nt][2*rh],     pb * h0), 0.f);
                        float p1 = fmaxf(fmaf(pa, acc[mt][nt][2*rh + 1], pb * h1), 0.f);
                        acc[mt][nt][2*rh]     = p0;
                        acc[mt][nt][2*rh + 1] = p1;
                        ps = fmaf(p0, p0, fmaf(p1, p1, ps));
                    }
                    ps += __shfl_xor_sync(0xffffffffu, ps, 1);
                    ps += __shfl_xor_sync(0xffffffffu, ps, 2);
                    psv[rh] = ps;
                }
                if (tq == 0) red2[slot_me + mt*8 + q] = make_float2(psv[0], psv[1]);
            }
            QUAD_BAR();   // C (bias path only)
            #pragma unroll
            for (int mt = 0; mt < 2; ++mt) {
                float Pt[2] = {0.f, 0.f};
                #pragma unroll
                for (int ww = 0; ww < 4; ++ww) {
                    float2 e = red2[slot_qb + ww*16 + mt*8 + q];
                    Pt[0] += e.x; Pt[1] += e.y;
                }
                #pragma unroll
                for (int rh = 0; rh < 2; ++rh) {
                    const int rloc = 16*mt + 8*rh + q;
                    float fs = final_scale(Pt[rh], LrL[mt][rh]);
                    float* outp = OUT + (unitRow + rloc) * 128 + 32*wq + 2*tq;
                    #pragma unroll
                    for (int nt = 0; nt < 4; ++nt) {
                        float2 o;
                        o.x = fs * acc[mt][nt][2*rh];
                        o.y = fs * acc[mt][nt][2*rh + 1];
                        *(float2*)(outp + 8*nt) = o;
                    }
                }
            }
        }
        // cross-iteration smem reuse ordered by the quad barriers
    }
}

extern "C" void kernel_launch(void* const* d_in, const int* in_sizes, int n_in,
                              void* d_out, int out_size) {
    const float* x = (const float*)d_in[0];
    const float* W = (const float*)d_in[1];
    const float* b = (const float*)d_in[2];
    float* out = (float*)d_out;

    int nRows  = in_sizes[0] / 128;      // 524288
    int nUnits = nRows / 32;             // 16384

    int sms = 148;
    cudaDeviceGetAttribute(&sms, cudaDevAttrMultiProcessorCount, 0);
    int grid = 3 * sms;                  // 3 persistent CTAs per SM, 2 quads each
    if (grid * 2 > nUnits) grid = (nUnits + 1) / 2;

    cudaFuncSetAttribute(blinear_fused,
                         cudaFuncAttributeMaxDynamicSharedMemorySize, SMEM_BYTES);
    blinear_fused<<<grid, 256, SMEM_BYTES>>>(x, W, b, out, nUnits);
}

// round 11
// speedup vs baseline: 1.1214x; 1.1214x over previous
#include <cuda_runtime.h>
#include <cuda_fp16.h>
#include <cstdint>

#define SM_STRIDE 136            // fp16 elems per smem row (conflict-free ldmatrix)

// smem byte offsets (per CTA ~54 KB -> 3 CTAs/SM)
#define WS_OFF    0                                  // W fp16: 128*136*2 = 34816
#define XS_OFF    34816                              // x fp16: 64 rows = 17408
#define XN2_OFF   (XS_OFF + 64 * SM_STRIDE * 2)      // float[64]
#define DS_OFF    (XN2_OFF + 256)                    // float[64]
#define US_OFF    (DS_OFF + 256)                     // float[128] u = W^T h
#define HV_OFF    (US_OFF + 512)                     // float[128]
#define RED1_OFF  (HV_OFF + 512)                     // float4[8][8] = 1024
#define RED2_OFF  (RED1_OFF + 1024)                  // float2[8][8] = 512
#define SC_OFF    (RED2_OFF + 512)                   // float[4]
#define SMEM_BYTES (SC_OFF + 16)

#define MINN  1e-15f
#define MAXN  0.996f
#define ATLIM (1.0f - 1e-7f)

#define LDSM4(R, addr)                                                        \
    asm volatile("ldmatrix.sync.aligned.m8n8.x4.shared.b16 {%0,%1,%2,%3}, [%4];" \
                 : "=r"((R)[0]), "=r"((R)[1]), "=r"((R)[2]), "=r"((R)[3])     \
                 : "r"(addr) : "memory")

#define PAIR_BAR() asm volatile("bar.sync %0, 64;" :: "r"(barid) : "memory")

__device__ __forceinline__ void mma16816(float* d, const uint32_t* a, const uint32_t* b) {
    asm volatile(
        "mma.sync.aligned.m16n8k16.row.col.f32.f16.f16.f32 "
        "{%0,%1,%2,%3}, {%4,%5,%6,%7}, {%8,%9}, {%0,%1,%2,%3};"
        : "+f"(d[0]), "+f"(d[1]), "+f"(d[2]), "+f"(d[3])
        : "r"(a[0]), "r"(a[1]), "r"(a[2]), "r"(a[3]), "r"(b[0]), "r"(b[1]));
}

__device__ __forceinline__ float artanh_c(float x) {
    float xc = fminf(x, ATLIM);
    return 0.5f * (log1pf(xc) - log1pf(-xc));
}

__device__ __forceinline__ void row_chain(float S2, float D, float xn2v, float y2,
                                          float& pa, float& pb, float& Lr) {
    float xn  = fmaxf(sqrtf(xn2v), MINN);
    float mxn = fmaxf(sqrtf(S2), MINN);
    float atx = artanh_c(xn);
    float r1  = tanhf(mxn / xn * atx);
    float scale1 = r1 / mxn;
    float resn = r1;
    float pn = fmaxf(resn, MINN);
    if (pn > MAXN) { scale1 *= MAXN / pn; resn = MAXN; }
    float x2 = resn * resn;
    float xy = scale1 * D;
    float num1 = 1.f + 2.f*xy + y2;
    float den  = fmaxf(1.f + 2.f*xy + x2*y2, MINN);
    float aC = num1 / den;
    float bC = (1.f - x2) / den;
    float o2n2 = aC*aC*x2 + 2.f*aC*bC*xy + bC*bC*y2;
    float o2n  = sqrtf(fmaxf(o2n2, 0.f));
    float g = 1.f;
    float pn2 = fmaxf(o2n, MINN);
    if (pn2 > MAXN) { g = MAXN / pn2; pn2 = MAXN; }
    Lr = artanh_c(pn2) / pn2;
    pa = g * aC * scale1;
    pb = g * bC;
}

__device__ __forceinline__ float final_scale(float ps, float Lr) {
    float P  = sqrtf(fmaxf(ps, 0.f));
    float un = fmaxf(Lr * P, MINN);
    float th = tanhf(un);
    float f  = th / un * Lr;
    if (th > MAXN) f *= MAXN / th;
    return f;
}

// fp32x4 -> fp16x4 (rn) into padded-stride smem
__device__ __forceinline__ void store_h16(__half* dst, int row, int col, float4 v) {
    __half2 h01 = __floats2half2_rn(v.x, v.y);
    __half2 h23 = __floats2half2_rn(v.z, v.w);
    uint2 ph;
    ph.x = *reinterpret_cast<uint32_t*>(&h01);
    ph.y = *reinterpret_cast<uint32_t*>(&h23);
    *(uint2*)(dst + row * SM_STRIDE + col) = ph;
}

__global__ void __launch_bounds__(256, 3)
blinear_fused(const float* __restrict__ X, const float* __restrict__ W,
              const float* __restrict__ B, float* __restrict__ OUT, int nTiles)
{
    extern __shared__ char smem[];
    __half* ws    = (__half*)(smem + WS_OFF);
    __half* xs    = (__half*)(smem + XS_OFF);
    float* xn2_s  = (float*)(smem + XN2_OFF);
    float* D_s    = (float*)(smem + DS_OFF);
    float* us     = (float*)(smem + US_OFF);
    float* hvec   = (float*)(smem + HV_OFF);
    float4* red1  = (float4*)(smem + RED1_OFF);
    float2* red2  = (float2*)(smem + RED2_OFF);
    float* SC     = (float*)(smem + SC_OFF);

    const int tid  = threadIdx.x;
    const int lane = tid & 31;
    const int w    = tid >> 5;   // 0..7
    const int pr   = w >> 1;     // pair 0..3 : rows 16*pr .. 16*pr+15
    const int wh   = w & 1;      // col half  : cols 64*wh .. 64*wh+63
    const int tq   = lane & 3;
    const int q    = lane >> 2;
    const int barid = 1 + pr;
    const int rbase = 16*pr + 8*wh;   // this warp's 8 load-rows within the tile
    const int lr   = lane >> 3;       // 0..3
    const int lc   = lane & 7;        // 0..7

    // ---- once per CTA: W (128x128) -> fp16 in smem ----
    #pragma unroll
    for (int j = 0; j < 16; ++j) {
        int row = j * 8 + w;
        float4 wv = *(const float4*)(W + (size_t)row * 128 + lane * 4);
        store_h16(ws, row, lane * 4, wv);
    }

    // ---- once per CTA: hyp_bias h = proj(expmap0(b)) (warp 0) ----
    if (w == 0) {
        float4 bv = *(const float4*)(B + lane * 4);
        float sq = bv.x*bv.x + bv.y*bv.y + bv.z*bv.z + bv.w*bv.w;
        #pragma unroll
        for (int o = 16; o; o >>= 1) sq += __shfl_xor_sync(0xffffffffu, sq, o);
        float bn2 = sq;
        float bn  = fmaxf(sqrtf(bn2), MINN);
        float th  = tanhf(bn);
        float hs  = th / bn;
        float hn  = hs * sqrtf(bn2);
        float pn  = fmaxf(hn, MINN);
        if (pn > MAXN) hs *= MAXN / pn;
        if (lane == 0) SC[0] = hs * hs * bn2;
        *(float4*)(hvec + lane * 4) =
            make_float4(hs*bv.x, hs*bv.y, hs*bv.z, hs*bv.w);
    }
    __syncthreads();

    const float y2 = SC[0];
    const bool hasB = (y2 != 0.0f);   // uniform across grid

    // ---- once per CTA (only if bias nonzero): u = W^T h ----
    if (hasB && tid < 128) {
        float a = 0.f;
        for (int j = 0; j < 128; ++j)
            a = fmaf(hvec[j], W[(size_t)j * 128 + tid], a);
        us[tid] = a;
    }
    __syncthreads();

    uint32_t s_xs = (uint32_t)__cvta_generic_to_shared(xs);
    uint32_t s_ws = (uint32_t)__cvta_generic_to_shared(ws);

    // A fragment address: pair rows 16*pr..16*pr+15 (one m16 frag)
    const uint32_t aoff = (uint32_t)(((16*pr + (lane & 15)) * SM_STRIDE + (lane >> 4) * 8) * 2);
    // B fragment addresses: 4 n16-groups covering this warp's 64 cols
    const int bg  = lane >> 3;
    const int b_n = ((bg >> 1) << 3) + (lane & 7);
    const int b_k = (bg & 1) * 8;
    uint32_t boff[4];
    #pragma unroll
    for (int g = 0; g < 4; ++g)
        boff[g] = (uint32_t)(((64*wh + 16*g + b_n) * SM_STRIDE + b_k) * 2);

    // exchange buffer slots
    const int slot_me = (pr*2 + wh    )*8 + q;
    const int slot_ot = (pr*2 + (wh^1))*8 + q;

    const int rl0 = 16*pr + q;       // local tile row for acc elems 0,1
    const int rl1 = rl0 + 8;         // local tile row for acc elems 2,3
    const int colbase = ((lc * 4) + (lr * 8)) & 31;

    // ================= persistent tile loop (64-row CTA tiles) ==============
    for (int tile = blockIdx.x; tile < nTiles; tile += gridDim.x) {
        const size_t tileRow = (size_t)tile * 64;

        // ---- load this warp's 8 rows (full 128 cols), norms, fp16 cvt ----
        #pragma unroll
        for (int j = 0; j < 2; ++j) {
            const int row = rbase + 4*j + lr;
            float sq = 0.f, dh = 0.f;
            #pragma unroll
            for (int i = 0; i < 4; ++i) {
                const int col = colbase + 32*i;
                float4 v = *(const float4*)(X + (tileRow + row) * 128 + col);
                sq = fmaf(v.x, v.x, fmaf(v.y, v.y, fmaf(v.z, v.z, fmaf(v.w, v.w, sq))));
                if (hasB) {
                    float4 u4 = *(const float4*)(us + col);
                    dh = fmaf(v.x, u4.x, fmaf(v.y, u4.y, fmaf(v.z, u4.z, fmaf(v.w, u4.w, dh))));
                }
                store_h16(xs, row, col, v);
            }
            #pragma unroll
            for (int o = 1; o <= 4; o <<= 1) {
                sq += __shfl_xor_sync(0xffffffffu, sq, o);
                if (hasB) dh += __shfl_xor_sync(0xffffffffu, dh, o);
            }
            if (lc == 0) { xn2_s[row] = sq; D_s[row] = dh; }
        }

        // L2 prefetch next tile's 8 rows for this warp (4 KB)
        {
            int nt2 = tile + gridDim.x;
            if (nt2 < nTiles) {
                const float* pf = X + ((size_t)nt2 * 64 + rbase) * 128 + (size_t)lane * 32;
                asm volatile("prefetch.global.L2 [%0];" :: "l"(pf));
            }
        }

        PAIR_BAR();   // A: xs + xn2 + D visible within pair

        // ---- MMA: 16 rows x 64 cols, single fp16 term ----
        float acc[8][4];
        #pragma unroll
        for (int nt = 0; nt < 8; ++nt)
            #pragma unroll
            for (int r = 0; r < 4; ++r) acc[nt][r] = 0.f;

        #pragma unroll
        for (int k = 0; k < 8; ++k) {
            const uint32_t kb = k * 32;
            uint32_t ah[4], bh[4][4];
            LDSM4(ah, s_xs + aoff + kb);
            #pragma unroll
            for (int g = 0; g < 4; ++g)
                LDSM4(bh[g], s_ws + boff[g] + kb);
            #pragma unroll
            for (int nt = 0; nt < 8; ++nt) {
                const int g = nt >> 1, o = (nt & 1) * 2;
                mma16816(acc[nt], ah, &bh[g][o]);
            }
        }

        // ---- phase 1: per-row sum(mx^2) AND sum(relu(mx)^2) ----
        float sq0 = 0.f, r0 = 0.f, sq1 = 0.f, r1 = 0.f;
        #pragma unroll
        for (int nt = 0; nt < 8; ++nt) {
            float v0 = acc[nt][0], v1 = acc[nt][1];
            float v2 = acc[nt][2], v3 = acc[nt][3];
            sq0 = fmaf(v0, v0, fmaf(v1, v1, sq0));
            sq1 = fmaf(v2, v2, fmaf(v3, v3, sq1));
            float p0 = fmaxf(v0, 0.f), p1 = fmaxf(v1, 0.f);
            float p2 = fmaxf(v2, 0.f), p3 = fmaxf(v3, 0.f);
            r0 = fmaf(p0, p0, fmaf(p1, p1, r0));
            r1 = fmaf(p2, p2, fmaf(p3, p3, r1));
        }
        #pragma unroll
        for (int o = 1; o <= 2; o <<= 1) {
            sq0 += __shfl_xor_sync(0xffffffffu, sq0, o);
            r0  += __shfl_xor_sync(0xffffffffu, r0,  o);
            sq1 += __shfl_xor_sync(0xffffffffu, sq1, o);
            r1  += __shfl_xor_sync(0xffffffffu, r1,  o);
        }
        if (tq == 0) red1[slot_me] = make_float4(sq0, r0, sq1, r1);
        PAIR_BAR();   // B
        float4 ot = red1[slot_ot];
        const float S2_0 = sq0 + ot.x, R_0 = r0 + ot.y;
        const float S2_1 = sq1 + ot.z, R_1 = r1 + ot.w;

        if (!hasB) {
            // ---- fast path: relu(pa*mx) = pa*relu(mx), no second exchange ----
            float pa0, pb0, Lr0, pa1, pb1, Lr1;
            row_chain(S2_0, 0.f, xn2_s[rl0], y2, pa0, pb0, Lr0);
            row_chain(S2_1, 0.f, xn2_s[rl1], y2, pa1, pb1, Lr1);
            float fac0 = final_scale(pa0 * pa0 * R_0, Lr0) * pa0;
            float fac1 = final_scale(pa1 * pa1 * R_1, Lr1) * pa1;
            float* outp = OUT + (tileRow + rl0) * 128 + 64*wh + 2*tq;
            #pragma unroll
            for (int nt = 0; nt < 8; ++nt) {
                float2 o0, o1;
                o0.x = fac0 * fmaxf(acc[nt][0], 0.f);
                o0.y = fac0 * fmaxf(acc[nt][1], 0.f);
                o1.x = fac1 * fmaxf(acc[nt][2], 0.f);
                o1.y = fac1 * fmaxf(acc[nt][3], 0.f);
                *(float2*)(outp + 8*nt)        = o0;
                *(float2*)(outp + 1024 + 8*nt) = o1;   // row rl1 = rl0 + 8
            }
        } else {
            // ---- general path: p = relu(pa*mx + pb*h), second exchange ----
            float pa0, pb0, Lr0, pa1, pb1, Lr1;
            row_chain(S2_0, D_s[rl0], xn2_s[rl0], y2, pa0, pb0, Lr0);
            row_chain(S2_1, D_s[rl1], xn2_s[rl1], y2, pa1, pb1, Lr1);
            float ps0 = 0.f, ps1 = 0.f;
            #pragma unroll
            for (int nt = 0; nt < 8; ++nt) {
                float h0 = hvec[64*wh + 8*nt + 2*tq];
                float h1 = hvec[64*wh + 8*nt + 2*tq + 1];
                float p0 = fmaxf(fmaf(pa0, acc[nt][0], pb0 * h0), 0.f);
                float p1 = fmaxf(fmaf(pa0, acc[nt][1], pb0 * h1), 0.f);
                float p2 = fmaxf(fmaf(pa1, acc[nt][2], pb1 * h0), 0.f);
                float p3 = fmaxf(fmaf(pa1, acc[nt][3], pb1 * h1), 0.f);
                acc[nt][0] = p0; acc[nt][1] = p1; acc[nt][2] = p2; acc[nt][3] = p3;
                ps0 = fmaf(p0, p0, fmaf(p1, p1, ps0));
                ps1 = fmaf(p2, p2, fmaf(p3, p3, ps1));
            }
            #pragma unroll
            for (int o = 1; o <= 2; o <<= 1) {
                ps0 += __shfl_xor_sync(0xffffffffu, ps0, o);
                ps1 += __shfl_xor_sync(0xffffffffu, ps1, o);
            }
            if (tq == 0) red2[slot_me] = make_float2(ps0, ps1);
            PAIR_BAR();   // C (bias path only)
            float2 ot2 = red2[slot_ot];
            float fs0 = final_scale(ps0 + ot2.x, Lr0);
            float fs1 = final_scale(ps1 + ot2.y, Lr1);
            float* outp = OUT + (tileRow + rl0) * 128 + 64*wh + 2*tq;
            #pragma unroll
            for (int nt = 0; nt < 8; ++nt) {
                float2 o0, o1;
                o0.x = fs0 * acc[nt][0];
                o0.y = fs0 * acc[nt][1];
                o1.x = fs1 * acc[nt][2];
                o1.y = fs1 * acc[nt][3];
                *(float2*)(outp + 8*nt)        = o0;
                *(float2*)(outp + 1024 + 8*nt) = o1;
            }
        }
        // cross-iteration smem reuse is ordered by the pair barriers
    }
}

extern "C" void kernel_launch(void* const* d_in, const int* in_sizes, int n_in,
                              void* d_out, int out_size) {
    const float* x = (const float*)d_in[0];
    const float* W = (const float*)d_in[1];
    const float* b = (const float*)d_in[2];
    float* out = (float*)d_out;

    int nRows  = in_sizes[0] / 128;      // 524288
    int nTiles = nRows / 64;             // 8192

    int sms = 148;
    cudaDeviceGetAttribute(&sms, cudaDevAttrMultiProcessorCount, 0);
    int grid = 3 * sms;                  // 3 persistent CTAs per SM
    if (grid > nTiles) grid = nTiles;

    cudaFuncSetAttribute(blinear_fused,
                         cudaFuncAttributeMaxDynamicSharedMemorySize, SMEM_BYTES);
    blinear_fused<<<grid, 256, SMEM_BYTES>>>(x, W, b, out, nTiles);
}

// round 12
// speedup vs baseline: 1.4411x; 1.2851x over previous
#include <cuda_runtime.h>
#include <cuda_fp16.h>
#include <cstdint>

#define SM_STRIDE 136            // fp16 elems per smem row (conflict-free ldmatrix)

// smem byte offsets (~75 KB -> 2 CTAs/SM)
#define WS_OFF    0                                  // W fp16: 128*136*2 = 34816
#define XS_OFF    34816                              // x fp16: 128 rows
#define XN2_OFF   (XS_OFF + 128 * SM_STRIDE * 2)     // float[128]
#define DS_OFF    (XN2_OFF + 512)                    // float[128]  per-row D = <x,u>
#define US_OFF    (DS_OFF + 512)                     // float[128]  u = W^T h
#define HV_OFF    (US_OFF + 512)                     // float[128]
#define RED1_OFF  (HV_OFF + 512)                     // float2[8][32] = 2048
#define RED2_OFF  (RED1_OFF + 2048)                  // float[8][32] = 1024
#define SC_OFF    (RED2_OFF + 1024)                  // float[4]
#define SMEM_BYTES (SC_OFF + 16)

#define MINN  1e-15f
#define MAXN  0.996f
#define ATLIM (1.0f - 1e-7f)

#define LDSM4(R, addr)                                                        \
    asm volatile("ldmatrix.sync.aligned.m8n8.x4.shared.b16 {%0,%1,%2,%3}, [%4];" \
                 : "=r"((R)[0]), "=r"((R)[1]), "=r"((R)[2]), "=r"((R)[3])     \
                 : "r"(addr) : "memory")

#define PAIR_BAR() asm volatile("bar.sync %0, 64;" :: "r"(barid) : "memory")

__device__ __forceinline__ void mma16816(float* d, const uint32_t* a, const uint32_t* b) {
    asm volatile(
        "mma.sync.aligned.m16n8k16.row.col.f32.f16.f16.f32 "
        "{%0,%1,%2,%3}, {%4,%5,%6,%7}, {%8,%9}, {%0,%1,%2,%3};"
        : "+f"(d[0]), "+f"(d[1]), "+f"(d[2]), "+f"(d[3])
        : "r"(a[0]), "r"(a[1]), "r"(a[2]), "r"(a[3]), "r"(b[0]), "r"(b[1]));
}

__device__ __forceinline__ float artanh_c(float x) {
    float xc = fminf(x, ATLIM);
    return 0.5f * (log1pf(xc) - log1pf(-xc));
}

__device__ __forceinline__ void row_chain(float S2, float D, float xn2v, float y2,
                                          float& pa, float& pb, float& Lr) {
    float xn  = fmaxf(sqrtf(xn2v), MINN);
    float mxn = fmaxf(sqrtf(S2), MINN);
    float atx = artanh_c(xn);
    float r1  = tanhf(mxn / xn * atx);
    float scale1 = r1 / mxn;
    float resn = r1;
    float pn = fmaxf(resn, MINN);
    if (pn > MAXN) { scale1 *= MAXN / pn; resn = MAXN; }
    float x2 = resn * resn;
    float xy = scale1 * D;
    float num1 = 1.f + 2.f*xy + y2;
    float den  = fmaxf(1.f + 2.f*xy + x2*y2, MINN);
    float aC = num1 / den;
    float bC = (1.f - x2) / den;
    float o2n2 = aC*aC*x2 + 2.f*aC*bC*xy + bC*bC*y2;
    float o2n  = sqrtf(fmaxf(o2n2, 0.f));
    float g = 1.f;
    float pn2 = fmaxf(o2n, MINN);
    if (pn2 > MAXN) { g = MAXN / pn2; pn2 = MAXN; }
    Lr = artanh_c(pn2) / pn2;
    pa = g * aC * scale1;
    pb = g * bC;
}

__device__ __forceinline__ float final_scale(float ps, float Lr) {
    float P  = sqrtf(fmaxf(ps, 0.f));
    float un = fmaxf(Lr * P, MINN);
    float th = tanhf(un);
    float f  = th / un * Lr;
    if (th > MAXN) f *= MAXN / th;
    return f;
}

// fp32x4 -> fp16x4 (rn) into padded-stride smem
__device__ __forceinline__ void store_h16(__half* dst, int row, int col, float4 v) {
    __half2 h01 = __floats2half2_rn(v.x, v.y);
    __half2 h23 = __floats2half2_rn(v.z, v.w);
    uint2 ph;
    ph.x = *reinterpret_cast<uint32_t*>(&h01);
    ph.y = *reinterpret_cast<uint32_t*>(&h23);
    *(uint2*)(dst + row * SM_STRIDE + col) = ph;
}

__global__ void __launch_bounds__(256, 2)
blinear_fused(const float* __restrict__ X, const float* __restrict__ W,
              const float* __restrict__ B, float* __restrict__ OUT, int nTiles)
{
    extern __shared__ char smem[];
    __half* ws    = (__half*)(smem + WS_OFF);
    __half* xs    = (__half*)(smem + XS_OFF);
    float* xn2_s  = (float*)(smem + XN2_OFF);
    float* D_s    = (float*)(smem + DS_OFF);
    float* us     = (float*)(smem + US_OFF);
    float* hvec   = (float*)(smem + HV_OFF);
    float2* red1  = (float2*)(smem + RED1_OFF);
    float* red2   = (float*)(smem + RED2_OFF);
    float* SC     = (float*)(smem + SC_OFF);

    const int tid  = threadIdx.x;
    const int lane = tid & 31;
    const int w    = tid >> 5;   // 0..7
    const int pr   = w >> 1;     // pair 0..3 : rows 32*pr .. 32*pr+31
    const int wh   = w & 1;      // col half  : cols 64*wh .. 64*wh+63
    const int tq   = lane & 3;
    const int q    = lane >> 2;
    const int barid = 1 + pr;
    const int rbase = 32*pr + 16*wh;   // this warp's 16 load-rows within the tile
    const int lr   = lane >> 3;        // 0..3
    const int lc   = lane & 7;         // 0..7

    // ---- once per CTA: W (128x128) -> fp16 in smem ----
    #pragma unroll
    for (int j = 0; j < 16; ++j) {
        int row = j * 8 + w;
        float4 wv = *(const float4*)(W + (size_t)row * 128 + lane * 4);
        store_h16(ws, row, lane * 4, wv);
    }

    // ---- once per CTA: hyp_bias h = proj(expmap0(b)) (warp 0) ----
    if (w == 0) {
        float4 bv = *(const float4*)(B + lane * 4);
        float sq = bv.x*bv.x + bv.y*bv.y + bv.z*bv.z + bv.w*bv.w;
        #pragma unroll
        for (int o = 16; o; o >>= 1) sq += __shfl_xor_sync(0xffffffffu, sq, o);
        float bn2 = sq;
        float bn  = fmaxf(sqrtf(bn2), MINN);
        float th  = tanhf(bn);
        float hs  = th / bn;
        float hn  = hs * sqrtf(bn2);
        float pn  = fmaxf(hn, MINN);
        if (pn > MAXN) hs *= MAXN / pn;
        if (lane == 0) SC[0] = hs * hs * bn2;
        *(float4*)(hvec + lane * 4) =
            make_float4(hs*bv.x, hs*bv.y, hs*bv.z, hs*bv.w);
    }
    __syncthreads();

    const float y2 = SC[0];
    const bool hasB = (y2 != 0.0f);   // uniform across grid

    // ---- once per CTA (only if bias nonzero): u = W^T h ----
    if (hasB && tid < 128) {
        float a = 0.f;
        for (int j = 0; j < 128; ++j)
            a = fmaf(hvec[j], W[(size_t)j * 128 + tid], a);
        us[tid] = a;
    }
    __syncthreads();

    uint32_t s_xs = (uint32_t)__cvta_generic_to_shared(xs);
    uint32_t s_ws = (uint32_t)__cvta_generic_to_shared(ws);

    // A fragment addresses: pair rows 32*pr..32*pr+31 (two m16 frags)
    const uint32_t aoff0 = (uint32_t)(((32*pr + (lane & 15)) * SM_STRIDE + (lane >> 4) * 8) * 2);
    const uint32_t aoff1 = aoff0 + 16 * SM_STRIDE * 2;
    // B fragment addresses: 4 n16-groups covering this warp's 64 cols
    const int bg  = lane >> 3;
    const int b_n = ((bg >> 1) << 3) + (lane & 7);
    const int b_k = (bg & 1) * 8;
    uint32_t boff[4];
    #pragma unroll
    for (int g = 0; g < 4; ++g)
        boff[g] = (uint32_t)(((64*wh + 16*g + b_n) * SM_STRIDE + b_k) * 2);

    // per-row exchange bases (32 rows per pair, one float2/row per col-half)
    const int ex_me = (pr*2 + wh    ) * 32;
    const int ex_ot = (pr*2 + (wh^1)) * 32;

    const int colbase = ((lc * 4) + (lr * 8)) & 31;

    // ================= persistent tile loop (128-row CTA tiles) =============
    for (int tile = blockIdx.x; tile < nTiles; tile += gridDim.x) {
        const size_t tileRow = (size_t)tile * 128;

        // ---- load 16 rows: 4 row-groups x 8 lanes x 4 chunks (coalesced) ----
        #pragma unroll
        for (int j = 0; j < 4; ++j) {
            const int row = rbase + 4*j + lr;
            float sq = 0.f, dh = 0.f;
            #pragma unroll
            for (int i = 0; i < 4; ++i) {
                const int col = colbase + 32*i;
                float4 v = *(const float4*)(X + (tileRow + row) * 128 + col);
                sq = fmaf(v.x, v.x, fmaf(v.y, v.y, fmaf(v.z, v.z, fmaf(v.w, v.w, sq))));
                if (hasB) {
                    float4 u4 = *(const float4*)(us + col);
                    dh = fmaf(v.x, u4.x, fmaf(v.y, u4.y, fmaf(v.z, u4.z, fmaf(v.w, u4.w, dh))));
                }
                store_h16(xs, row, col, v);
            }
            #pragma unroll
            for (int o = 1; o <= 4; o <<= 1) {
                sq += __shfl_xor_sync(0xffffffffu, sq, o);
                if (hasB) dh += __shfl_xor_sync(0xffffffffu, dh, o);
            }
            if (lc == 0) { xn2_s[row] = sq; D_s[row] = dh; }
        }

        // L2 prefetch next tile's 16 rows for this warp (8 KB)
        {
            int nt2 = tile + gridDim.x;
            if (nt2 < nTiles) {
                const float* pf = X + ((size_t)nt2 * 128 + rbase) * 128
                                    + (size_t)lane * 64;
                asm volatile("prefetch.global.L2 [%0];" :: "l"(pf));
                asm volatile("prefetch.global.L2 [%0];" :: "l"(pf + 32));
            }
        }

        PAIR_BAR();   // A: xs + xn2 + D visible within pair

        // ---- MMA: 32 rows x 64 cols, single fp16 term ----
        float acc[2][8][4];
        #pragma unroll
        for (int mt = 0; mt < 2; ++mt)
            #pragma unroll
            for (int nt = 0; nt < 8; ++nt)
                #pragma unroll
                for (int r = 0; r < 4; ++r) acc[mt][nt][r] = 0.f;

        #pragma unroll
        for (int k = 0; k < 8; ++k) {
            const uint32_t kb = k * 32;
            uint32_t ah0[4], ah1[4];
            LDSM4(ah0, s_xs + aoff0 + kb);
            LDSM4(ah1, s_xs + aoff1 + kb);
            uint32_t bh[4][4];
            #pragma unroll
            for (int g = 0; g < 4; ++g)
                LDSM4(bh[g], s_ws + boff[g] + kb);
            #pragma unroll
            for (int nt = 0; nt < 8; ++nt) {
                const int g = nt >> 1, o = (nt & 1) * 2;
                mma16816(acc[0][nt], ah0, &bh[g][o]);
                mma16816(acc[1][nt], ah1, &bh[g][o]);
            }
        }

        // ---- phase 1: per-row sum(mx^2) AND sum(relu(mx)^2); acc<-relu (fast) ----
        #pragma unroll
        for (int mt = 0; mt < 2; ++mt) {
            float sq0 = 0.f, r0 = 0.f, sq1 = 0.f, r1 = 0.f;
            #pragma unroll
            for (int nt = 0; nt < 8; ++nt) {
                float v0 = acc[mt][nt][0], v1 = acc[mt][nt][1];
                float v2 = acc[mt][nt][2], v3 = acc[mt][nt][3];
                sq0 = fmaf(v0, v0, fmaf(v1, v1, sq0));
                sq1 = fmaf(v2, v2, fmaf(v3, v3, sq1));
                float p0 = fmaxf(v0, 0.f), p1 = fmaxf(v1, 0.f);
                float p2 = fmaxf(v2, 0.f), p3 = fmaxf(v3, 0.f);
                r0 = fmaf(p0, p0, fmaf(p1, p1, r0));
                r1 = fmaf(p2, p2, fmaf(p3, p3, r1));
                if (!hasB) {  // pre-relu values not needed again on fast path
                    acc[mt][nt][0] = p0; acc[mt][nt][1] = p1;
                    acc[mt][nt][2] = p2; acc[mt][nt][3] = p3;
                }
            }
            #pragma unroll
            for (int o = 1; o <= 2; o <<= 1) {
                sq0 += __shfl_xor_sync(0xffffffffu, sq0, o);
                r0  += __shfl_xor_sync(0xffffffffu, r0,  o);
                sq1 += __shfl_xor_sync(0xffffffffu, sq1, o);
                r1  += __shfl_xor_sync(0xffffffffu, r1,  o);
            }
            if (tq == 0) {
                red1[ex_me + 16*mt + q]     = make_float2(sq0, r0);
                red1[ex_me + 16*mt + 8 + q] = make_float2(sq1, r1);
            }
        }
        PAIR_BAR();   // B

        // ---- lane-parallel scalar chain: lane = local row 0..31 of this pair ----
        float2 aP = red1[ex_me + lane];
        float2 bP = red1[ex_ot + lane];
        float S2 = aP.x + bP.x;
        float Rr = aP.y + bP.y;
        float pa, pb, Lr;
        row_chain(S2, hasB ? D_s[32*pr + lane] : 0.f,
                  xn2_s[32*pr + lane], y2, pa, pb, Lr);

        if (!hasB) {
            // relu(pa*mx) = pa*relu(mx); fac folds everything into one multiplier
            float fac = final_scale(pa * pa * Rr, Lr) * pa;
            float fv[2][2];
            fv[0][0] = __shfl_sync(0xffffffffu, fac, q);
            fv[0][1] = __shfl_sync(0xffffffffu, fac, q + 8);
            fv[1][0] = __shfl_sync(0xffffffffu, fac, q + 16);
            fv[1][1] = __shfl_sync(0xffffffffu, fac, q + 24);
            #pragma unroll
            for (int mt = 0; mt < 2; ++mt)
                #pragma unroll
                for (int rh = 0; rh < 2; ++rh) {
                    const float fs = fv[mt][rh];
                    float* outp = OUT + (tileRow + 32*pr + 16*mt + 8*rh + q) * 128
                                      + 64*wh + 2*tq;
                    #pragma unroll
                    for (int nt = 0; nt < 8; ++nt) {
                        float2 o;
                        o.x = fs * acc[mt][nt][2*rh];       // acc already relu'd
                        o.y = fs * acc[mt][nt][2*rh + 1];
                        *(float2*)(outp + 8*nt) = o;
                    }
                }
        } else {
            // ---- general path: p = relu(pa*mx + pb*h), second exchange ----
            float paM[2][2], pbM[2][2];
            #pragma unroll
            for (int mt = 0; mt < 2; ++mt)
                #pragma unroll
                for (int rh = 0; rh < 2; ++rh) {
                    paM[mt][rh] = __shfl_sync(0xffffffffu, pa, 16*mt + 8*rh + q);
                    pbM[mt][rh] = __shfl_sync(0xffffffffu, pb, 16*mt + 8*rh + q);
                }
            #pragma unroll
            for (int mt = 0; mt < 2; ++mt)
                #pragma unroll
                for (int rh = 0; rh < 2; ++rh) {
                    float ps = 0.f;
                    const float pav = paM[mt][rh], pbv = pbM[mt][rh];
                    #pragma unroll
                    for (int nt = 0; nt < 8; ++nt) {
                        float h0 = hvec[64*wh + 8*nt + 2*tq];
                        float h1 = hvec[64*wh + 8*nt + 2*tq + 1];
                        float p0 = fmaxf(fmaf(pav, acc[mt][nt][2*rh],     pbv * h0), 0.f);
                        float p1 = fmaxf(fmaf(pav, acc[mt][nt][2*rh + 1], pbv * h1), 0.f);
                        acc[mt][nt][2*rh]     = p0;
                        acc[mt][nt][2*rh + 1] = p1;
                        ps = fmaf(p0, p0, fmaf(p1, p1, ps));
                    }
                    ps += __shfl_xor_sync(0xffffffffu, ps, 1);
                    ps += __shfl_xor_sync(0xffffffffu, ps, 2);
                    if (tq == 0) red2[ex_me + 16*mt + 8*rh + q] = ps;
                }
            PAIR_BAR();   // C (bias path only)
            float pst = red2[ex_me + lane] + red2[ex_ot + lane];
            float fs_l = final_scale(pst, Lr);
            float fv[2][2];
            fv[0][0] = __shfl_sync(0xffffffffu, fs_l, q);
            fv[0][1] = __shfl_sync(0xffffffffu, fs_l, q + 8);
            fv[1][0] = __shfl_sync(0xffffffffu, fs_l, q + 16);
            fv[1][1] = __shfl_sync(0xffffffffu, fs_l, q + 24);
            #pragma unroll
            for (int mt = 0; mt < 2; ++mt)
                #pragma unroll
                for (int rh = 0; rh < 2; ++rh) {
                    const float fs = fv[mt][rh];
                    float* outp = OUT + (tileRow + 32*pr + 16*mt + 8*rh + q) * 128
                                      + 64*wh + 2*tq;
                    #pragma unroll
                    for (int nt = 0; nt < 8; ++nt) {
                        float2 o;
                        o.x = fs * acc[mt][nt][2*rh];
                        o.y = fs * acc[mt][nt][2*rh + 1];
                        *(float2*)(outp + 8*nt) = o;
                    }
                }
        }
        // cross-iteration smem reuse is ordered by the pair barriers
    }
}

extern "C" void kernel_launch(void* const* d_in, const int* in_sizes, int n_in,
                              void* d_out, int out_size) {
    const float* x = (const float*)d_in[0];
    const float* W = (const float*)d_in[1];
    const float* b = (const float*)d_in[2];
    float* out = (float*)d_out;

    int nRows  = in_sizes[0] / 128;      // 524288
    int nTiles = nRows / 128;            // 4096

    int sms = 148;
    cudaDeviceGetAttribute(&sms, cudaDevAttrMultiProcessorCount, 0);
    int grid = 2 * sms;                  // 2 persistent CTAs per SM
    if (grid > nTiles) grid = nTiles;

    cudaFuncSetAttribute(blinear_fused,
                         cudaFuncAttributeMaxDynamicSharedMemorySize, SMEM_BYTES);
    blinear_fused<<<grid, 256, SMEM_BYTES>>>(x, W, b, out, nTiles);
}